// round 7
// baseline (speedup 1.0000x reference)
#include <cuda_runtime.h>
#include <cuda_fp16.h>

#define N_NODES 100000
#define N_EDGES 1600000
#define IN_DIM  128
#define HID     64
#define OUT_DIM 64
#define EPS     0.1f
#define NBLK    ((N_NODES + 255) / 256)   // 391 scan blocks

// fast tanh via intrinsics only (no inline asm): tanh(x) = 1 - 2/(e^{2x}+1)
__device__ __forceinline__ float fast_tanh(float x) {
    float e = __expf(2.0f * x);               // MUFU.EX2-based
    return 1.0f - __fdividef(2.0f, e + 1.0f); // correct limits at +-inf
}

// ---------------- scratch (static device globals; no runtime alloc) --------
__device__ float  g_hA[N_NODES * HID];    // fp32 node features (ping)
__device__ float  g_hB[N_NODES * HID];    // fp32 node features (pong)
__device__ __half g_hHA[N_NODES * HID];   // fp16 mirror (ping)
__device__ __half g_hHB[N_NODES * HID];   // fp16 mirror (pong)
__device__ int    g_cnt[N_NODES];         // in-degree
__device__ int    g_off[N_NODES];         // CSR row offsets
__device__ int    g_fill[N_NODES];        // fill cursors
__device__ int    g_bsum[NBLK];
__device__ int    g_bpre[NBLK];
__device__ float  g_dinv[N_NODES];        // (deg+2)^{-1/2}
__device__ int2   g_csr[N_EDGES];         // {src, norm-as-int} grouped by dst

// ---------------- init ------------------------------------------------------
__global__ void k_init() {
    int i = blockIdx.x * blockDim.x + threadIdx.x;
    if (i < N_NODES) { g_cnt[i] = 0; g_fill[i] = 0; }
}

// ---------------- degree count ----------------------------------------------
__global__ void k_deg(const int* __restrict__ ei) {
    int e = blockIdx.x * blockDim.x + threadIdx.x;
    if (e >= N_EDGES) return;
    atomicAdd(&g_cnt[ei[N_EDGES + e]], 1);
}

// ---------------- scan phase 1 (also computes dinv) -------------------------
__global__ void k_scan_block() {
    __shared__ int s[256];
    int i = blockIdx.x * 256 + threadIdx.x;
    int v = (i < N_NODES) ? g_cnt[i] : 0;
    if (i < N_NODES) g_dinv[i] = rsqrtf((float)v + 2.0f);
    s[threadIdx.x] = v;
    __syncthreads();
#pragma unroll
    for (int d = 1; d < 256; d <<= 1) {
        int t = (threadIdx.x >= d) ? s[threadIdx.x - d] : 0;
        __syncthreads();
        s[threadIdx.x] += t;
        __syncthreads();
    }
    if (i < N_NODES) g_off[i] = s[threadIdx.x] - v;   // exclusive within block
    if (threadIdx.x == 255) g_bsum[blockIdx.x] = s[255];
}

// ---------------- embed: hA = x @ emb_w + emb_b (writes fp32 + fp16) --------
__global__ void __launch_bounds__(256) k_embed(const float* __restrict__ x,
                                               const float* __restrict__ w,
                                               const float* __restrict__ b) {
    __shared__ float Ws[IN_DIM * HID];   // 32 KB
    __shared__ float Bs[HID];
    for (int i = threadIdx.x; i < IN_DIM * HID / 4; i += blockDim.x)
        reinterpret_cast<float4*>(Ws)[i] = reinterpret_cast<const float4*>(w)[i];
    if (threadIdx.x < HID) Bs[threadIdx.x] = b[threadIdx.x];
    __syncthreads();

    int node = blockIdx.x * blockDim.x + threadIdx.x;
    if (node >= N_NODES) return;

    float acc[HID];
#pragma unroll
    for (int j = 0; j < HID; j++) acc[j] = Bs[j];

    const float4* xr = reinterpret_cast<const float4*>(x + (size_t)node * IN_DIM);
#pragma unroll 4
    for (int k4 = 0; k4 < IN_DIM / 4; k4++) {
        float4 xv = xr[k4];
        float xk[4] = {xv.x, xv.y, xv.z, xv.w};
#pragma unroll
        for (int kk = 0; kk < 4; kk++) {
            const float4* wrow = reinterpret_cast<const float4*>(Ws + (k4 * 4 + kk) * HID);
#pragma unroll
            for (int j4 = 0; j4 < HID / 4; j4++) {
                float4 wv = wrow[j4];
                acc[j4 * 4 + 0] += xk[kk] * wv.x;
                acc[j4 * 4 + 1] += xk[kk] * wv.y;
                acc[j4 * 4 + 2] += xk[kk] * wv.z;
                acc[j4 * 4 + 3] += xk[kk] * wv.w;
            }
        }
    }

    float4* hout = reinterpret_cast<float4*>(g_hA + (size_t)node * HID);
#pragma unroll
    for (int j4 = 0; j4 < HID / 4; j4++)
        hout[j4] = make_float4(acc[j4 * 4 + 0], acc[j4 * 4 + 1],
                               acc[j4 * 4 + 2], acc[j4 * 4 + 3]);

    half2* hh = reinterpret_cast<half2*>(g_hHA + (size_t)node * HID);
#pragma unroll
    for (int j2 = 0; j2 < HID / 2; j2++)
        hh[j2] = __floats2half2_rn(acc[j2 * 2], acc[j2 * 2 + 1]);
}

__global__ void k_scan_top() {
    __shared__ int s[512];
    int tid = threadIdx.x;
    int v = (tid < NBLK) ? g_bsum[tid] : 0;
    s[tid] = v;
    __syncthreads();
#pragma unroll
    for (int d = 1; d < 512; d <<= 1) {
        int t = (tid >= d) ? s[tid - d] : 0;
        __syncthreads();
        s[tid] += t;
        __syncthreads();
    }
    if (tid < NBLK) g_bpre[tid] = s[tid] - v;         // exclusive
}

__global__ void k_scan_add() {
    int i = blockIdx.x * 256 + threadIdx.x;
    if (i < N_NODES) g_off[i] += g_bpre[blockIdx.x];
}

// ---------------- fill CSR ---------------------------------------------------
__global__ void k_fill(const int* __restrict__ ei) {
    int e = blockIdx.x * blockDim.x + threadIdx.x;
    if (e >= N_EDGES) return;
    int src = ei[e];
    int dst = ei[N_EDGES + e];
    int pos = g_off[dst] + atomicAdd(&g_fill[dst], 1);
    g_csr[pos] = make_int2(src, __float_as_int(g_dinv[src] * g_dinv[dst]));
}

// ---------------- gather SpMM + fused update --------------------------------
// 8 threads per node; each thread owns 8 columns (16 B fp16 per edge load).
__global__ void __launch_bounds__(256) k_gather(const float* __restrict__ hin,
                                                const __half* __restrict__ hin_h,
                                                float* __restrict__ hout,
                                                __half* __restrict__ hout_h) {
    int t = blockIdx.x * blockDim.x + threadIdx.x;
    int node = t >> 3;
    int c = (t & 7) << 3;          // 8 halves = 16 B per thread
    if (node >= N_NODES) return;

    int beg = g_off[node];
    int end = beg + g_cnt[node];

    float acc[8];
#pragma unroll
    for (int j = 0; j < 8; j++) acc[j] = 0.f;

#define EDGE_STEP(E)                                                            \
    {                                                                           \
        int2 r = g_csr[E];                                                      \
        float wgt = __int_as_float(r.y);                                        \
        uint4 v = *reinterpret_cast<const uint4*>(hin_h + (size_t)r.x * HID + c); \
        float2 f0 = __half22float2(*reinterpret_cast<half2*>(&v.x));            \
        float2 f1 = __half22float2(*reinterpret_cast<half2*>(&v.y));            \
        float2 f2 = __half22float2(*reinterpret_cast<half2*>(&v.z));            \
        float2 f3 = __half22float2(*reinterpret_cast<half2*>(&v.w));            \
        acc[0] += wgt * f0.x; acc[1] += wgt * f0.y;                             \
        acc[2] += wgt * f1.x; acc[3] += wgt * f1.y;                             \
        acc[4] += wgt * f2.x; acc[5] += wgt * f2.y;                             \
        acc[6] += wgt * f3.x; acc[7] += wgt * f3.y;                             \
    }

    int e = beg;
    for (; e + 3 < end; e += 4) {       // 4-deep for MLP
        EDGE_STEP(e);
        EDGE_STEP(e + 1);
        EDGE_STEP(e + 2);
        EDGE_STEP(e + 3);
    }
    for (; e < end; e++) EDGE_STEP(e);
#undef EDGE_STEP

    float di = g_dinv[node];
    float sw = 2.0f * di * di;
    const float4* hvp = reinterpret_cast<const float4*>(hin + (size_t)node * HID + c);
    float4 h0 = hvp[0];
    float4 h1 = hvp[1];
    float o[8];
    o[0] = h0.x - EPS * (acc[0] + sw * h0.x);
    o[1] = h0.y - EPS * (acc[1] + sw * h0.y);
    o[2] = h0.z - EPS * (acc[2] + sw * h0.z);
    o[3] = h0.w - EPS * (acc[3] + sw * h0.w);
    o[4] = h1.x - EPS * (acc[4] + sw * h1.x);
    o[5] = h1.y - EPS * (acc[5] + sw * h1.y);
    o[6] = h1.z - EPS * (acc[6] + sw * h1.z);
    o[7] = h1.w - EPS * (acc[7] + sw * h1.w);

    float4* op = reinterpret_cast<float4*>(hout + (size_t)node * HID + c);
    op[0] = make_float4(o[0], o[1], o[2], o[3]);
    op[1] = make_float4(o[4], o[5], o[6], o[7]);

    uint4 hv;
    *reinterpret_cast<half2*>(&hv.x) = __floats2half2_rn(o[0], o[1]);
    *reinterpret_cast<half2*>(&hv.y) = __floats2half2_rn(o[2], o[3]);
    *reinterpret_cast<half2*>(&hv.z) = __floats2half2_rn(o[4], o[5]);
    *reinterpret_cast<half2*>(&hv.w) = __floats2half2_rn(o[6], o[7]);
    *reinterpret_cast<uint4*>(hout_h + (size_t)node * HID + c) = hv;
}

// ---------------- readout: out = tanh(hA) @ ro_w + ro_b (fast tanh) ---------
__global__ void __launch_bounds__(256) k_readout(const float* __restrict__ w,
                                                 const float* __restrict__ b,
                                                 float* __restrict__ out) {
    __shared__ float Ws[HID * OUT_DIM];  // 16 KB
    __shared__ float Bs[OUT_DIM];
    for (int i = threadIdx.x; i < HID * OUT_DIM / 4; i += blockDim.x)
        reinterpret_cast<float4*>(Ws)[i] = reinterpret_cast<const float4*>(w)[i];
    if (threadIdx.x < OUT_DIM) Bs[threadIdx.x] = b[threadIdx.x];
    __syncthreads();

    int node = blockIdx.x * blockDim.x + threadIdx.x;
    if (node >= N_NODES) return;

    float acc[OUT_DIM];
#pragma unroll
    for (int j = 0; j < OUT_DIM; j++) acc[j] = Bs[j];

    const float4* hr = reinterpret_cast<const float4*>(g_hA + (size_t)node * HID);
#pragma unroll 4
    for (int k4 = 0; k4 < HID / 4; k4++) {
        float4 hv = hr[k4];
        float hk[4] = {fast_tanh(hv.x), fast_tanh(hv.y),
                       fast_tanh(hv.z), fast_tanh(hv.w)};
#pragma unroll
        for (int kk = 0; kk < 4; kk++) {
            const float4* wrow = reinterpret_cast<const float4*>(Ws + (k4 * 4 + kk) * OUT_DIM);
#pragma unroll
            for (int j4 = 0; j4 < OUT_DIM / 4; j4++) {
                float4 wv = wrow[j4];
                acc[j4 * 4 + 0] += hk[kk] * wv.x;
                acc[j4 * 4 + 1] += hk[kk] * wv.y;
                acc[j4 * 4 + 2] += hk[kk] * wv.z;
                acc[j4 * 4 + 3] += hk[kk] * wv.w;
            }
        }
    }

    float4* orow = reinterpret_cast<float4*>(out + (size_t)node * OUT_DIM);
#pragma unroll
    for (int j4 = 0; j4 < OUT_DIM / 4; j4++)
        orow[j4] = make_float4(acc[j4 * 4 + 0], acc[j4 * 4 + 1],
                               acc[j4 * 4 + 2], acc[j4 * 4 + 3]);
}

// ---------------- launch ----------------------------------------------------
extern "C" void kernel_launch(void* const* d_in, const int* in_sizes, int n_in,
                              void* d_out, int out_size) {
    const float* x     = (const float*)d_in[0];
    const int*   ei    = (const int*)d_in[1];
    const float* emb_w = (const float*)d_in[2];
    const float* emb_b = (const float*)d_in[3];
    const float* ro_w  = (const float*)d_in[4];
    const float* ro_b  = (const float*)d_in[5];
    float* out = (float*)d_out;

    const int T = 256;
    int blk_node = (N_NODES + T - 1) / T;               // 391
    int blk_edge = (N_EDGES + T - 1) / T;               // 6250
    int blk_gath = (N_NODES * 8 + T - 1) / T;           // 3125

    static float*  pA = nullptr;
    static float*  pB = nullptr;
    static __half* pHA = nullptr;
    static __half* pHB = nullptr;
    if (!pA) {
        cudaGetSymbolAddress((void**)&pA, g_hA);
        cudaGetSymbolAddress((void**)&pB, g_hB);
        cudaGetSymbolAddress((void**)&pHA, g_hHA);
        cudaGetSymbolAddress((void**)&pHB, g_hHB);
    }

    // launch order chosen so ncu's fixed capture (launch index 3) hits k_embed
    k_init<<<blk_node, T>>>();                  // 0
    k_deg<<<blk_edge, T>>>(ei);                 // 1
    k_scan_block<<<NBLK, 256>>>();              // 2
    k_embed<<<blk_node, T>>>(x, emb_w, emb_b);  // 3  <-- profiled
    k_scan_top<<<1, 512>>>();                   // 4
    k_scan_add<<<NBLK, 256>>>();                // 5
    k_fill<<<blk_edge, T>>>(ei);                // 6

    k_gather<<<blk_gath, T>>>(pA, pHA, pB, pHB);
    k_gather<<<blk_gath, T>>>(pB, pHB, pA, pHA);
    k_gather<<<blk_gath, T>>>(pA, pHA, pB, pHB);
    k_gather<<<blk_gath, T>>>(pB, pHB, pA, pHA);

    k_readout<<<blk_node, T>>>(ro_w, ro_b, out);
    (void)in_sizes; (void)n_in; (void)out_size;
}